// round 1
// baseline (speedup 1.0000x reference)
#include <cuda_runtime.h>
#include <math.h>

// Problem constants
#define B_    1024
#define F_    4096
#define V_    20000
#define E_    512
#define H_    1024
#define L_    20
#define D_    4
#define FOURH 4096

// ---------------------------------------------------------------------------
// Scratch (device globals — no allocation allowed)
// ---------------------------------------------------------------------------
__device__ float g_x[B_ * E_];            // current input embedding
__device__ float g_h[B_ * H_];            // hidden
__device__ float g_c[B_ * H_];            // cell
__device__ float g_gates[B_ * FOURH];     // LSTM gates
__device__ float g_logits[B_ * V_];       // sender logits (80 MB)
__device__ int   g_msg[L_ * B_];          // greedy tokens
__device__ float g_lp[B_];                // log-prob of last token
__device__ float g_r[B_ * F_];            // receiver projection
__device__ float g_ts[B_ * B_];           // target scores
__device__ float g_ds[D_ * B_ * B_];      // distractor scores
__device__ float g_rowLoss[B_];
__device__ float g_rowCorr[B_];

// ---------------------------------------------------------------------------
// Generic SGEMM: C[M,N] = A[M,K] @ W[N,K]^T (+ bias[N]) (+= C if accum)
// 128x128 block tile, BK=16, 8x8 per thread, 256 threads.
// M must be a multiple of 128 (true for all call sites); K multiple of 16;
// N guarded (V=20000 is not a multiple of 128).
// ---------------------------------------------------------------------------
__global__ __launch_bounds__(256) void gemm_abt(
    const float* __restrict__ A, const float* __restrict__ W,
    const float* __restrict__ bias, float* __restrict__ C,
    int M, int N, int K, int accum)
{
    __shared__ float As[16][128];
    __shared__ float Ws[16][128];

    const int t  = threadIdx.x;
    const int tx = t & 15;          // 0..15 -> N sub-tiles
    const int ty = t >> 4;          // 0..15 -> M sub-tiles
    const int row0 = blockIdx.y * 128;
    const int col0 = blockIdx.x * 128;
    const int lr = t >> 1;          // 0..127 row within tile for loads
    const int lc = (t & 1) << 3;    // 0 or 8 (K offset)

    float acc[8][8];
#pragma unroll
    for (int i = 0; i < 8; i++)
#pragma unroll
        for (int j = 0; j < 8; j++) acc[i][j] = 0.f;

    const int wr = col0 + lr;
    const float* ap = A + (size_t)(row0 + lr) * K + lc;
    const float* wp = (wr < N) ? (W + (size_t)wr * K + lc) : (const float*)0;

    for (int k0 = 0; k0 < K; k0 += 16) {
        float4 a0 = *(const float4*)(ap + k0);
        float4 a1 = *(const float4*)(ap + k0 + 4);
        As[lc + 0][lr] = a0.x; As[lc + 1][lr] = a0.y;
        As[lc + 2][lr] = a0.z; As[lc + 3][lr] = a0.w;
        As[lc + 4][lr] = a1.x; As[lc + 5][lr] = a1.y;
        As[lc + 6][lr] = a1.z; As[lc + 7][lr] = a1.w;

        float4 w0 = make_float4(0.f, 0.f, 0.f, 0.f);
        float4 w1 = make_float4(0.f, 0.f, 0.f, 0.f);
        if (wp) { w0 = *(const float4*)(wp + k0); w1 = *(const float4*)(wp + k0 + 4); }
        Ws[lc + 0][lr] = w0.x; Ws[lc + 1][lr] = w0.y;
        Ws[lc + 2][lr] = w0.z; Ws[lc + 3][lr] = w0.w;
        Ws[lc + 4][lr] = w1.x; Ws[lc + 5][lr] = w1.y;
        Ws[lc + 6][lr] = w1.z; Ws[lc + 7][lr] = w1.w;
        __syncthreads();

#pragma unroll
        for (int k = 0; k < 16; k++) {
            float a[8], b[8];
            *(float4*)(a)     = *(const float4*)&As[k][ty * 8];
            *(float4*)(a + 4) = *(const float4*)&As[k][ty * 8 + 4];
            *(float4*)(b)     = *(const float4*)&Ws[k][tx * 8];
            *(float4*)(b + 4) = *(const float4*)&Ws[k][tx * 8 + 4];
#pragma unroll
            for (int i = 0; i < 8; i++)
#pragma unroll
                for (int j = 0; j < 8; j++)
                    acc[i][j] += a[i] * b[j];
        }
        __syncthreads();
    }

#pragma unroll
    for (int i = 0; i < 8; i++) {
        const int r = row0 + ty * 8 + i;
        float* crow = C + (size_t)r * N;
#pragma unroll
        for (int j = 0; j < 8; j++) {
            const int cN = col0 + tx * 8 + j;
            if (cN < N) {
                float v = acc[i][j];
                if (bias)  v += bias[cN];
                if (accum) v += crow[cN];
                crow[cN] = v;
            }
        }
    }
}

// ---------------------------------------------------------------------------
// LSTM pointwise update: gate order i, f, g, o (torch LSTMCell)
// ---------------------------------------------------------------------------
__device__ __forceinline__ float sigf(float x) { return 1.f / (1.f + expf(-x)); }

__global__ __launch_bounds__(256) void lstm_update(
    const float* __restrict__ gates, float* __restrict__ h, float* __restrict__ c)
{
    int idx = blockIdx.x * 256 + threadIdx.x;     // over B*H
    int b = idx >> 10;                            // H_ = 1024
    int j = idx & 1023;
    const float* g = gates + (size_t)b * FOURH;
    float ig = sigf(g[j]);
    float fg = sigf(g[H_ + j]);
    float gg = tanhf(g[2 * H_ + j]);
    float og = sigf(g[3 * H_ + j]);
    float cn = fg * c[idx] + ig * gg;
    c[idx] = cn;
    h[idx] = og * tanhf(cn);
}

// ---------------------------------------------------------------------------
// Per-row argmax + log-softmax value at argmax (deterministic block tree)
// lp = logit_max - logsumexp = -log(sum exp(l - max))
// ---------------------------------------------------------------------------
__global__ __launch_bounds__(256) void row_argmax_lse(
    const float* __restrict__ logits, int* __restrict__ tok, float* __restrict__ lp)
{
    const int b = blockIdx.x, t = threadIdx.x;
    const float* row = logits + (size_t)b * V_;

    float m = -3.402823466e38f;
    int   mi = 0;
    for (int j = t; j < V_; j += 256) {
        float v = row[j];
        if (v > m) { m = v; mi = j; }        // keeps first (lowest j) on ties
    }
    __shared__ float sm[256];
    __shared__ int   si[256];
    sm[t] = m; si[t] = mi;
    __syncthreads();
    for (int s = 128; s; s >>= 1) {
        if (t < s) {
            float vo = sm[t + s]; int io = si[t + s];
            if (vo > sm[t] || (vo == sm[t] && io < si[t])) { sm[t] = vo; si[t] = io; }
        }
        __syncthreads();
    }
    const float M = sm[0];
    const int   idx = si[0];

    float sum = 0.f;
    for (int j = t; j < V_; j += 256) sum += expf(row[j] - M);
    __shared__ float ss[256];
    ss[t] = sum;
    __syncthreads();
    for (int s = 128; s; s >>= 1) { if (t < s) ss[t] += ss[t + s]; __syncthreads(); }
    if (t == 0) { tok[b] = idx; lp[b] = -logf(ss[0]); }
}

// ---------------------------------------------------------------------------
// Embedding gather / start-token broadcast
// ---------------------------------------------------------------------------
__global__ __launch_bounds__(256) void gather_emb(
    const float* __restrict__ emb, const int* __restrict__ idx, float* __restrict__ x)
{
    int i = blockIdx.x * 256 + threadIdx.x;       // over B*E
    int b = i >> 9;                               // E_ = 512
    int e = i & 511;
    x[i] = emb[(size_t)idx[b] * E_ + e];
}

__global__ __launch_bounds__(256) void init_x0(
    const float* __restrict__ emb_s, const int* __restrict__ start, float* __restrict__ x)
{
    int i = blockIdx.x * 256 + threadIdx.x;
    int e = i & 511;
    x[i] = emb_s[(size_t)(*start) * E_ + e];
}

// ---------------------------------------------------------------------------
// Hinge loss + accuracy: one block per row i, deterministic reductions
// ---------------------------------------------------------------------------
__global__ __launch_bounds__(256) void loss_acc_rows(
    const float* __restrict__ ts, const float* __restrict__ ds,
    const float* __restrict__ lp, float* __restrict__ rowLoss, float* __restrict__ rowCorr)
{
    const int i = blockIdx.x, t = threadIdx.x;
    const float* tsr = ts + (size_t)i * B_;
    const float* d0r = ds + (size_t)0 * B_ * B_ + (size_t)i * B_;
    const float* d1r = ds + (size_t)1 * B_ * B_ + (size_t)i * B_;
    const float* d2r = ds + (size_t)2 * B_ * B_ + (size_t)i * B_;
    const float* d3r = ds + (size_t)3 * B_ * B_ + (size_t)i * B_;

    float lsum = 0.f, tp = 0.f, dp0 = 0.f, dp1 = 0.f, dp2 = 0.f, dp3 = 0.f;
    for (int j = t; j < B_; j += 256) {
        float tv = tsr[j];
        float v0 = d0r[j], v1 = d1r[j], v2 = d2r[j], v3 = d3r[j];
        float hng = fmaxf(0.f, 1.f - tv + v0) + fmaxf(0.f, 1.f - tv + v1)
                  + fmaxf(0.f, 1.f - tv + v2) + fmaxf(0.f, 1.f - tv + v3);
        lsum += hng * (-lp[j]);
        tp  += expf(tv);
        dp0 += expf(v0); dp1 += expf(v1); dp2 += expf(v2); dp3 += expf(v3);
    }
    __shared__ float sh[6][256];
    sh[0][t] = lsum; sh[1][t] = tp; sh[2][t] = dp0;
    sh[3][t] = dp1;  sh[4][t] = dp2; sh[5][t] = dp3;
    __syncthreads();
    for (int s = 128; s; s >>= 1) {
        if (t < s)
#pragma unroll
            for (int q = 0; q < 6; q++) sh[q][t] += sh[q][t + s];
        __syncthreads();
    }
    if (t == 0) {
        rowLoss[i] = sh[0][0];
        float tpv = sh[1][0];
        // argmax over [tp, dp0..dp3] == 0  <=>  tp >= all dp (ties -> index 0)
        rowCorr[i] = (tpv >= sh[2][0] && tpv >= sh[3][0] &&
                      tpv >= sh[4][0] && tpv >= sh[5][0]) ? 1.f : 0.f;
    }
}

__global__ __launch_bounds__(256) void finalize_k(
    const float* __restrict__ rowLoss, const float* __restrict__ rowCorr,
    float* __restrict__ out)
{
    const int t = threadIdx.x;
    float a = 0.f, b = 0.f;
    for (int i = t; i < B_; i += 256) { a += rowLoss[i]; b += rowCorr[i]; }
    __shared__ float sa[256], sb[256];
    sa[t] = a; sb[t] = b;
    __syncthreads();
    for (int s = 128; s; s >>= 1) {
        if (t < s) { sa[t] += sa[t + s]; sb[t] += sb[t + s]; }
        __syncthreads();
    }
    if (t == 0) {
        out[0] = sa[0] / ((float)B_ * (float)B_);   // loss
        out[1] = sb[0] / (float)B_;                 // accuracy
    }
}

// ---------------------------------------------------------------------------
// Launch sequence (graph-capturable: kernels + async memsets only)
// ---------------------------------------------------------------------------
extern "C" void kernel_launch(void* const* d_in, const int* in_sizes, int n_in,
                              void* d_out, int out_size)
{
    (void)in_sizes; (void)n_in; (void)out_size;
    const float* target   = (const float*)d_in[0];
    const float* distr    = (const float*)d_in[1];
    const int*   start    = (const int*)  d_in[2];
    /* d_in[3] = max_sentence_length = 20 (hardcoded; scalar unreadable under capture) */
    const float* emb_s    = (const float*)d_in[4];
    const float* Wih_s    = (const float*)d_in[5];
    const float* Whh_s    = (const float*)d_in[6];
    const float* bih_s    = (const float*)d_in[7];
    const float* bhh_s    = (const float*)d_in[8];
    const float* aff_s_W  = (const float*)d_in[9];
    const float* aff_s_b  = (const float*)d_in[10];
    const float* probs_W  = (const float*)d_in[11];
    const float* probs_b  = (const float*)d_in[12];
    const float* emb_r    = (const float*)d_in[13];
    const float* Wih_r    = (const float*)d_in[14];
    const float* Whh_r    = (const float*)d_in[15];
    const float* bih_r    = (const float*)d_in[16];
    const float* bhh_r    = (const float*)d_in[17];
    const float* aff_r_W  = (const float*)d_in[18];
    const float* aff_r_b  = (const float*)d_in[19];
    float* out = (float*)d_out;

    float *x, *h, *c, *gates, *logits, *lp, *r, *ts, *ds, *rowLoss, *rowCorr;
    int* msg;
    cudaGetSymbolAddress((void**)&x,       g_x);
    cudaGetSymbolAddress((void**)&h,       g_h);
    cudaGetSymbolAddress((void**)&c,       g_c);
    cudaGetSymbolAddress((void**)&gates,   g_gates);
    cudaGetSymbolAddress((void**)&logits,  g_logits);
    cudaGetSymbolAddress((void**)&msg,     g_msg);
    cudaGetSymbolAddress((void**)&lp,      g_lp);
    cudaGetSymbolAddress((void**)&r,       g_r);
    cudaGetSymbolAddress((void**)&ts,      g_ts);
    cudaGetSymbolAddress((void**)&ds,      g_ds);
    cudaGetSymbolAddress((void**)&rowLoss, g_rowLoss);
    cudaGetSymbolAddress((void**)&rowCorr, g_rowCorr);

    const dim3 gGate(FOURH / 128, B_ / 128);
    const dim3 gLogit((V_ + 127) / 128, B_ / 128);

    // ---- Sender ----
    gemm_abt<<<dim3(H_ / 128, B_ / 128), 256>>>(target, aff_s_W, aff_s_b, h, B_, H_, F_, 0);
    cudaMemsetAsync(c, 0, sizeof(float) * B_ * H_);
    init_x0<<<(B_ * E_) / 256, 256>>>(emb_s, start, x);

    for (int t = 0; t < L_; t++) {
        gemm_abt<<<gGate, 256>>>(x, Wih_s, bih_s, gates, B_, FOURH, E_, 0);
        gemm_abt<<<gGate, 256>>>(h, Whh_s, bhh_s, gates, B_, FOURH, H_, 1);
        lstm_update<<<(B_ * H_) / 256, 256>>>(gates, h, c);
        gemm_abt<<<gLogit, 256>>>(h, probs_W, probs_b, logits, B_, V_, H_, 0);
        row_argmax_lse<<<B_, 256>>>(logits, msg + t * B_, lp);
        if (t + 1 < L_) gather_emb<<<(B_ * E_) / 256, 256>>>(emb_s, msg + t * B_, x);
    }

    // ---- Receiver ----
    cudaMemsetAsync(h, 0, sizeof(float) * B_ * H_);
    cudaMemsetAsync(c, 0, sizeof(float) * B_ * H_);
    for (int t = 0; t < L_; t++) {
        gather_emb<<<(B_ * E_) / 256, 256>>>(emb_r, msg + t * B_, x);
        gemm_abt<<<gGate, 256>>>(x, Wih_r, bih_r, gates, B_, FOURH, E_, 0);
        gemm_abt<<<gGate, 256>>>(h, Whh_r, bhh_r, gates, B_, FOURH, H_, 1);
        lstm_update<<<(B_ * H_) / 256, 256>>>(gates, h, c);
    }

    // ---- Scores + loss/accuracy ----
    gemm_abt<<<dim3(F_ / 128, B_ / 128), 256>>>(h, aff_r_W, aff_r_b, r, B_, F_, H_, 0);
    gemm_abt<<<dim3(B_ / 128, B_ / 128), 256>>>(target, r, (const float*)0, ts, B_, B_, F_, 0);
    gemm_abt<<<dim3(B_ / 128, (D_ * B_) / 128), 256>>>(distr, r, (const float*)0, ds, D_ * B_, B_, F_, 0);
    loss_acc_rows<<<B_, 256>>>(ts, ds, lp, rowLoss, rowCorr);
    finalize_k<<<1, 256>>>(rowLoss, rowCorr, out);
}

// round 9
// speedup vs baseline: 1.4316x; 1.4316x over previous
#include <cuda_runtime.h>
#include <cstdint>
#include <math.h>

// Problem constants
#define B_    1024
#define F_    4096
#define V_    20000
#define E_    512
#define H_    1024
#define L_    20
#define D_    4
#define FOURH 4096

// ---------------------------------------------------------------------------
// Scratch (device globals — no allocation allowed)
// ---------------------------------------------------------------------------
__device__ float g_x[B_ * E_];
__device__ float g_h[B_ * H_];
__device__ float g_c[B_ * H_];
__device__ float g_gates[B_ * FOURH];
__device__ float g_logits[B_ * V_];
__device__ int   g_msg[L_ * B_];
__device__ float g_lp[B_];
__device__ float g_r[B_ * F_];
__device__ float g_ts[B_ * B_];
__device__ float g_ds[D_ * B_ * B_];
__device__ float g_rowLoss[B_];
__device__ float g_rowCorr[B_];

// ---------------------------------------------------------------------------
// mma.sync tf32 GEMM (base-ISA; works on target sm_103) with 3xTF32 accuracy.
// C[M,N] = A0[M,K0]@W0[N,K0]^T (+ A1[M,K1]@W1[N,K1]^T) (+ bias0 + bias1)
// 128x128x32 tiles, 256 threads (8 warps, 2x4), warp tile 64x32 (4x4 m16n8k8).
// Smem: raw fp32 tiles, row-major [128][36] padded (conflict-free frag loads),
// double buffered via cp.async. 73728 B total.
// ---------------------------------------------------------------------------
#define PADK 36
#define TILE_F (128 * PADK)            // floats per tile buffer (4608)
#define GEMM_SMEM (2 * 2 * TILE_F * 4) // 73728 bytes

__device__ __forceinline__ uint32_t smem_u32(const void* p) {
    uint32_t a;
    asm("{ .reg .u64 t; cvta.to.shared.u64 t, %1; cvt.u32.u64 %0, t; }" : "=r"(a) : "l"(p));
    return a;
}

__device__ __forceinline__ void split1(float f, uint32_t& hi, uint32_t& lo) {
    uint32_t h;
    asm("cvt.rna.tf32.f32 %0, %1;" : "=r"(h) : "f"(f));
    float l = f - __uint_as_float(h);
    uint32_t lw;
    asm("cvt.rna.tf32.f32 %0, %1;" : "=r"(lw) : "f"(l));
    hi = h; lo = lw;
}

__device__ __forceinline__ void mma8(float* c, const uint32_t* a, const uint32_t* b) {
    asm volatile(
        "mma.sync.aligned.m16n8k8.row.col.f32.tf32.tf32.f32 "
        "{%0,%1,%2,%3}, {%4,%5,%6,%7}, {%8,%9}, {%0,%1,%2,%3};"
        : "+f"(c[0]), "+f"(c[1]), "+f"(c[2]), "+f"(c[3])
        : "r"(a[0]), "r"(a[1]), "r"(a[2]), "r"(a[3]), "r"(b[0]), "r"(b[1]));
}

__device__ __forceinline__ void cp16(uint32_t dst, const void* src, uint32_t srcsz) {
    asm volatile("cp.async.cg.shared.global [%0], [%1], 16, %2;"
                 :: "r"(dst), "l"(src), "r"(srcsz) : "memory");
}

// Load one 128x32 A tile + 128x32 W tile into buffer q via cp.async.
__device__ __forceinline__ void load_tile(
    uint32_t sb, int q, const float* __restrict__ A, const float* __restrict__ W,
    int K, int kb, int row0, int col0, int N, int t)
{
    const uint32_t abase = sb + (uint32_t)q * (2u * TILE_F * 4u);
    const uint32_t bbase = abase + TILE_F * 4u;
#pragma unroll
    for (int i = 0; i < 4; i++) {
        int ci = t + 256 * i;           // 0..1023
        int row = ci >> 3;
        int cc = ci & 7;
        uint32_t off = (uint32_t)(row * PADK + cc * 4) * 4u;
        cp16(abase + off, A + (size_t)(row0 + row) * K + kb + cc * 4, 16);
        int n = col0 + row;
        const float* wsrc = W + (size_t)(n < N ? n : 0) * K + kb + cc * 4;
        cp16(bbase + off, wsrc, (n < N) ? 16u : 0u);
    }
}

__global__ __launch_bounds__(256) void gemm_mma(
    const float* __restrict__ A0, const float* __restrict__ W0, int K0,
    const float* __restrict__ A1, const float* __restrict__ W1, int K1,
    const float* __restrict__ bias0, const float* __restrict__ bias1,
    float* __restrict__ C, int M, int N)
{
    extern __shared__ float smemf[];
    const uint32_t sb = smem_u32(smemf);
    const int t = threadIdx.x, wid = t >> 5, lane = t & 31;
    const int g = lane >> 2, t4 = lane & 3;
    const int warp_m = wid & 1, warp_n = wid >> 1;   // 2 x 4
    const int row0 = blockIdx.y * 128, col0 = blockIdx.x * 128;

    const int T0 = K0 >> 5;
    const int T1 = A1 ? (K1 >> 5) : 0;
    const int T = T0 + T1;

    float acc[4][4][4];
#pragma unroll
    for (int mt = 0; mt < 4; mt++)
#pragma unroll
        for (int nt = 0; nt < 4; nt++)
#pragma unroll
            for (int i = 0; i < 4; i++) acc[mt][nt][i] = 0.f;

    // prologue: tile 0 -> buffer 0
    {
        const float* A = A0; const float* W = W0; int K = K0;
        if (T0 == 0) { A = A1; W = W1; K = K1; }
        load_tile(sb, 0, A, W, K, 0, row0, col0, N, t);
        asm volatile("cp.async.commit_group;" ::: "memory");
    }

    for (int tt = 0; tt < T; tt++) {
        if (tt + 1 < T) {
            int nt_ = tt + 1;
            const float* A; const float* W; int K, kb;
            if (nt_ < T0) { A = A0; W = W0; K = K0; kb = nt_ << 5; }
            else          { A = A1; W = W1; K = K1; kb = (nt_ - T0) << 5; }
            load_tile(sb, nt_ & 1, A, W, K, kb, row0, col0, N, t);
            asm volatile("cp.async.commit_group;" ::: "memory");
            asm volatile("cp.async.wait_group 1;" ::: "memory");
        } else {
            asm volatile("cp.async.wait_group 0;" ::: "memory");
        }
        __syncthreads();

        const float* As = smemf + (tt & 1) * (2 * TILE_F);
        const float* Bs = As + TILE_F;

#pragma unroll
        for (int kk = 0; kk < 4; kk++) {
            const int kb = kk * 8;
            uint32_t ahi[4][4], alo[4][4];
#pragma unroll
            for (int mt = 0; mt < 4; mt++) {
                const int mr = warp_m * 64 + mt * 16 + g;
                split1(As[mr * PADK + kb + t4],            ahi[mt][0], alo[mt][0]);
                split1(As[(mr + 8) * PADK + kb + t4],      ahi[mt][1], alo[mt][1]);
                split1(As[mr * PADK + kb + t4 + 4],        ahi[mt][2], alo[mt][2]);
                split1(As[(mr + 8) * PADK + kb + t4 + 4],  ahi[mt][3], alo[mt][3]);
            }
            uint32_t bhi[4][2], blo[4][2];
#pragma unroll
            for (int nt = 0; nt < 4; nt++) {
                const int nr = warp_n * 32 + nt * 8 + g;
                split1(Bs[nr * PADK + kb + t4],       bhi[nt][0], blo[nt][0]);
                split1(Bs[nr * PADK + kb + t4 + 4],   bhi[nt][1], blo[nt][1]);
            }
#pragma unroll
            for (int mt = 0; mt < 4; mt++)
#pragma unroll
                for (int nt = 0; nt < 4; nt++) {
                    mma8(acc[mt][nt], alo[mt], bhi[nt]);
                    mma8(acc[mt][nt], ahi[mt], blo[nt]);
                    mma8(acc[mt][nt], ahi[mt], bhi[nt]);
                }
        }
        __syncthreads();
    }

    // epilogue
#pragma unroll
    for (int mt = 0; mt < 4; mt++) {
        const int rg = row0 + warp_m * 64 + mt * 16 + g;
#pragma unroll
        for (int nt = 0; nt < 4; nt++) {
            const int col = col0 + warp_n * 32 + nt * 8 + t4 * 2;
            if (col < N) {      // N even, col even -> col+1 valid too
                float bv0 = 0.f, bv1 = 0.f;
                if (bias0) { bv0 = bias0[col]; bv1 = bias0[col + 1]; }
                if (bias1) { bv0 += bias1[col]; bv1 += bias1[col + 1]; }
                float2 v0 = make_float2(acc[mt][nt][0] + bv0, acc[mt][nt][1] + bv1);
                float2 v1 = make_float2(acc[mt][nt][2] + bv0, acc[mt][nt][3] + bv1);
                *(float2*)(C + (size_t)rg * N + col) = v0;
                *(float2*)(C + (size_t)(rg + 8) * N + col) = v1;
            }
        }
    }
}

// ---------------------------------------------------------------------------
// LSTM pointwise update: gate order i, f, g, o
// ---------------------------------------------------------------------------
__device__ __forceinline__ float sigf(float x) { return 1.f / (1.f + expf(-x)); }

__global__ __launch_bounds__(256) void lstm_update(
    const float* __restrict__ gates, float* __restrict__ h, float* __restrict__ c)
{
    int idx = blockIdx.x * 256 + threadIdx.x;
    int b = idx >> 10;
    int j = idx & 1023;
    const float* g = gates + (size_t)b * FOURH;
    float ig = sigf(g[j]);
    float fg = sigf(g[H_ + j]);
    float gg = tanhf(g[2 * H_ + j]);
    float og = sigf(g[3 * H_ + j]);
    float cn = fg * c[idx] + ig * gg;
    c[idx] = cn;
    h[idx] = og * tanhf(cn);
}

// ---------------------------------------------------------------------------
// Per-row argmax + log-softmax value at argmax
// ---------------------------------------------------------------------------
__global__ __launch_bounds__(256) void row_argmax_lse(
    const float* __restrict__ logits, int* __restrict__ tok, float* __restrict__ lp)
{
    const int b = blockIdx.x, t = threadIdx.x;
    const float* row = logits + (size_t)b * V_;

    float m = -3.402823466e38f;
    int   mi = 0;
    for (int j = t; j < V_; j += 256) {
        float v = row[j];
        if (v > m) { m = v; mi = j; }
    }
    __shared__ float sm[256];
    __shared__ int   si[256];
    sm[t] = m; si[t] = mi;
    __syncthreads();
    for (int s = 128; s; s >>= 1) {
        if (t < s) {
            float vo = sm[t + s]; int io = si[t + s];
            if (vo > sm[t] || (vo == sm[t] && io < si[t])) { sm[t] = vo; si[t] = io; }
        }
        __syncthreads();
    }
    const float M = sm[0];
    const int   idx = si[0];

    float sum = 0.f;
    for (int j = t; j < V_; j += 256) sum += expf(row[j] - M);
    __shared__ float ss[256];
    ss[t] = sum;
    __syncthreads();
    for (int s = 128; s; s >>= 1) { if (t < s) ss[t] += ss[t + s]; __syncthreads(); }
    if (t == 0) { tok[b] = idx; lp[b] = -logf(ss[0]); }
}

// ---------------------------------------------------------------------------
// Embedding gather / start-token broadcast
// ---------------------------------------------------------------------------
__global__ __launch_bounds__(256) void gather_emb(
    const float* __restrict__ emb, const int* __restrict__ idx, float* __restrict__ x)
{
    int i = blockIdx.x * 256 + threadIdx.x;
    int b = i >> 9;
    int e = i & 511;
    x[i] = emb[(size_t)idx[b] * E_ + e];
}

__global__ __launch_bounds__(256) void init_x0(
    const float* __restrict__ emb_s, const int* __restrict__ start, float* __restrict__ x)
{
    int i = blockIdx.x * 256 + threadIdx.x;
    int e = i & 511;
    x[i] = emb_s[(size_t)(*start) * E_ + e];
}

// ---------------------------------------------------------------------------
// Hinge loss + accuracy
// ---------------------------------------------------------------------------
__global__ __launch_bounds__(256) void loss_acc_rows(
    const float* __restrict__ ts, const float* __restrict__ ds,
    const float* __restrict__ lp, float* __restrict__ rowLoss, float* __restrict__ rowCorr)
{
    const int i = blockIdx.x, t = threadIdx.x;
    const float* tsr = ts + (size_t)i * B_;
    const float* d0r = ds + (size_t)0 * B_ * B_ + (size_t)i * B_;
    const float* d1r = ds + (size_t)1 * B_ * B_ + (size_t)i * B_;
    const float* d2r = ds + (size_t)2 * B_ * B_ + (size_t)i * B_;
    const float* d3r = ds + (size_t)3 * B_ * B_ + (size_t)i * B_;

    float lsum = 0.f, tp = 0.f, dp0 = 0.f, dp1 = 0.f, dp2 = 0.f, dp3 = 0.f;
    for (int j = t; j < B_; j += 256) {
        float tv = tsr[j];
        float v0 = d0r[j], v1 = d1r[j], v2 = d2r[j], v3 = d3r[j];
        float hng = fmaxf(0.f, 1.f - tv + v0) + fmaxf(0.f, 1.f - tv + v1)
                  + fmaxf(0.f, 1.f - tv + v2) + fmaxf(0.f, 1.f - tv + v3);
        lsum += hng * (-lp[j]);
        tp  += expf(tv);
        dp0 += expf(v0); dp1 += expf(v1); dp2 += expf(v2); dp3 += expf(v3);
    }
    __shared__ float sh[6][256];
    sh[0][t] = lsum; sh[1][t] = tp; sh[2][t] = dp0;
    sh[3][t] = dp1;  sh[4][t] = dp2; sh[5][t] = dp3;
    __syncthreads();
    for (int s = 128; s; s >>= 1) {
        if (t < s)
#pragma unroll
            for (int q = 0; q < 6; q++) sh[q][t] += sh[q][t + s];
        __syncthreads();
    }
    if (t == 0) {
        rowLoss[i] = sh[0][0];
        float tpv = sh[1][0];
        rowCorr[i] = (tpv >= sh[2][0] && tpv >= sh[3][0] &&
                      tpv >= sh[4][0] && tpv >= sh[5][0]) ? 1.f : 0.f;
    }
}

__global__ __launch_bounds__(256) void finalize_k(
    const float* __restrict__ rowLoss, const float* __restrict__ rowCorr,
    float* __restrict__ out)
{
    const int t = threadIdx.x;
    float a = 0.f, b = 0.f;
    for (int i = t; i < B_; i += 256) { a += rowLoss[i]; b += rowCorr[i]; }
    __shared__ float sa[256], sb[256];
    sa[t] = a; sb[t] = b;
    __syncthreads();
    for (int s = 128; s; s >>= 1) {
        if (t < s) { sa[t] += sa[t + s]; sb[t] += sb[t + s]; }
        __syncthreads();
    }
    if (t == 0) {
        out[0] = sa[0] / ((float)B_ * (float)B_);
        out[1] = sb[0] / (float)B_;
    }
}

// ---------------------------------------------------------------------------
// Launch sequence
// ---------------------------------------------------------------------------
extern "C" void kernel_launch(void* const* d_in, const int* in_sizes, int n_in,
                              void* d_out, int out_size)
{
    (void)in_sizes; (void)n_in; (void)out_size;
    const float* target   = (const float*)d_in[0];
    const float* distr    = (const float*)d_in[1];
    const int*   start    = (const int*)  d_in[2];
    const float* emb_s    = (const float*)d_in[4];
    const float* Wih_s    = (const float*)d_in[5];
    const float* Whh_s    = (const float*)d_in[6];
    const float* bih_s    = (const float*)d_in[7];
    const float* bhh_s    = (const float*)d_in[8];
    const float* aff_s_W  = (const float*)d_in[9];
    const float* aff_s_b  = (const float*)d_in[10];
    const float* probs_W  = (const float*)d_in[11];
    const float* probs_b  = (const float*)d_in[12];
    const float* emb_r    = (const float*)d_in[13];
    const float* Wih_r    = (const float*)d_in[14];
    const float* Whh_r    = (const float*)d_in[15];
    const float* bih_r    = (const float*)d_in[16];
    const float* bhh_r    = (const float*)d_in[17];
    const float* aff_r_W  = (const float*)d_in[18];
    const float* aff_r_b  = (const float*)d_in[19];
    float* out = (float*)d_out;

    float *x, *h, *c, *gates, *logits, *lp, *r, *ts, *ds, *rowLoss, *rowCorr;
    int* msg;
    cudaGetSymbolAddress((void**)&x,       g_x);
    cudaGetSymbolAddress((void**)&h,       g_h);
    cudaGetSymbolAddress((void**)&c,       g_c);
    cudaGetSymbolAddress((void**)&gates,   g_gates);
    cudaGetSymbolAddress((void**)&logits,  g_logits);
    cudaGetSymbolAddress((void**)&msg,     g_msg);
    cudaGetSymbolAddress((void**)&lp,      g_lp);
    cudaGetSymbolAddress((void**)&r,       g_r);
    cudaGetSymbolAddress((void**)&ts,      g_ts);
    cudaGetSymbolAddress((void**)&ds,      g_ds);
    cudaGetSymbolAddress((void**)&rowLoss, g_rowLoss);
    cudaGetSymbolAddress((void**)&rowCorr, g_rowCorr);

    cudaFuncSetAttribute(gemm_mma, cudaFuncAttributeMaxDynamicSharedMemorySize, GEMM_SMEM);

    const float* NUL = (const float*)0;
    const dim3 gGate(FOURH / 128, B_ / 128);       // 32 x 8
    const dim3 gLogit((V_ + 127) / 128, B_ / 128); // 157 x 8

    // ---- Sender ----
    gemm_mma<<<dim3(H_ / 128, B_ / 128), 256, GEMM_SMEM>>>(
        target, aff_s_W, F_, NUL, NUL, 0, aff_s_b, NUL, h, B_, H_);
    cudaMemsetAsync(c, 0, sizeof(float) * B_ * H_);
    init_x0<<<(B_ * E_) / 256, 256>>>(emb_s, start, x);

    for (int t = 0; t < L_; t++) {
        gemm_mma<<<gGate, 256, GEMM_SMEM>>>(
            x, Wih_s, E_, h, Whh_s, H_, bih_s, bhh_s, gates, B_, FOURH);
        lstm_update<<<(B_ * H_) / 256, 256>>>(gates, h, c);
        gemm_mma<<<gLogit, 256, GEMM_SMEM>>>(
            h, probs_W, H_, NUL, NUL, 0, probs_b, NUL, logits, B_, V_);
        row_argmax_lse<<<B_, 256>>>(logits, msg + t * B_, lp);
        if (t + 1 < L_) gather_emb<<<(B_ * E_) / 256, 256>>>(emb_s, msg + t * B_, x);
    }

    // ---- Receiver ----
    cudaMemsetAsync(h, 0, sizeof(float) * B_ * H_);
    cudaMemsetAsync(c, 0, sizeof(float) * B_ * H_);
    for (int t = 0; t < L_; t++) {
        gather_emb<<<(B_ * E_) / 256, 256>>>(emb_r, msg + t * B_, x);
        gemm_mma<<<gGate, 256, GEMM_SMEM>>>(
            x, Wih_r, E_, h, Whh_r, H_, bih_r, bhh_r, gates, B_, FOURH);
        lstm_update<<<(B_ * H_) / 256, 256>>>(gates, h, c);
    }

    // ---- Scores + loss/accuracy ----
    gemm_mma<<<dim3(F_ / 128, B_ / 128), 256, GEMM_SMEM>>>(
        h, aff_r_W, H_, NUL, NUL, 0, aff_r_b, NUL, r, B_, F_);
    gemm_mma<<<dim3(B_ / 128, B_ / 128), 256, GEMM_SMEM>>>(
        target, r, F_, NUL, NUL, 0, NUL, NUL, ts, B_, B_);
    gemm_mma<<<dim3(B_ / 128, (D_ * B_) / 128), 256, GEMM_SMEM>>>(
        distr, r, F_, NUL, NUL, 0, NUL, NUL, ds, D_ * B_, B_);
    loss_acc_rows<<<B_, 256>>>(ts, ds, lp, rowLoss, rowCorr);
    finalize_k<<<1, 256>>>(rowLoss, rowCorr, out);
}